// round 10
// baseline (speedup 1.0000x reference)
#include <cuda_runtime.h>
#include <math.h>

#define NB 4
#define CIN 256
#define COUT 128
#define HH 64
#define WW 64
#define HO 128
#define WO 128
#define KK9 9
#define CK (CIN*KK9)   // 2304

// ---- scratch (device globals; no allocation) ----
__device__ float g_xn[NB*HH*WW*CIN];        // x in NHWC, 16 MB
__device__ float g_om[NB*27*HH*WW];         // offset conv output, NCHW
__device__ float g_wT[CK*COUT];             // dcn weights (c*9+k, o)
__device__ float g_wTo[CK*32];              // offconv weights (c*9+k, co) padded 27->32
__device__ float g_wT2[16*COUT*COUT];       // deconv weights (tap, i, o)
__device__ float g_y1[NB*HH*WW*COUT];       // dcn output NHWC (pre-BN)
__device__ float g_z[NB*HO*WO*COUT];        // deconv output NHWC (pre-BN)
__device__ float g_part1[256*2*COUT];
__device__ float g_part2[512*2*COUT];
__device__ float g_scale1[COUT], g_shift1[COUT];
__device__ float g_scale2[COUT], g_shift2[COUT];

// ---- packed fp32x2 helpers (sm_103a FFMA2) ----
__device__ __forceinline__ unsigned long long pack2(float v) {
    unsigned long long r;
    asm("mov.b64 %0, {%1, %1};" : "=l"(r) : "f"(v));
    return r;
}
__device__ __forceinline__ void fma2(unsigned long long& a, unsigned long long v, unsigned long long w) {
    asm("fma.rn.f32x2 %0, %1, %2, %0;" : "+l"(a) : "l"(v), "l"(w));
}
__device__ __forceinline__ void add2(unsigned long long& a, unsigned long long b) {
    asm("add.rn.f32x2 %0, %0, %1;" : "+l"(a) : "l"(b));
}
__device__ __forceinline__ float2 unpack2(unsigned long long a) {
    float2 f;
    asm("mov.b64 {%0, %1}, %2;" : "=f"(f.x), "=f"(f.y) : "l"(a));
    return f;
}

// ---- 1. transpose x NCHW -> NHWC ----
__global__ void k_transpose_x(const float* __restrict__ x) {
    int idx = blockIdx.x * blockDim.x + threadIdx.x;  // over NB*HH*WW*CIN
    if (idx >= NB*HH*WW*CIN) return;
    int c = idx & (CIN-1);
    int pix = idx >> 8;
    int b = pix >> 12;
    int h = (pix >> 6) & 63;
    int w = pix & 63;
    g_xn[idx] = x[((b*CIN + c)*HH + h)*WW + w];
}

// ---- 2. reorder dcn weights: wT[(c*9+k)*128 + o] = w_dcn[o][c][k] ----
__global__ void k_reorder_wdcn(const float* __restrict__ w_dcn) {
    int idx = blockIdx.x * blockDim.x + threadIdx.x;
    if (idx >= CK*COUT) return;
    int o = idx & 127;
    int ck = idx >> 7;
    g_wT[idx] = w_dcn[o*CK + ck];
}

// ---- 2b. reorder offset-conv weights: wTo[ck*32 + co] = w_off[co][ck], pad ----
__global__ void k_reorder_woff(const float* __restrict__ w_off) {
    int idx = blockIdx.x * blockDim.x + threadIdx.x;
    if (idx >= CK*32) return;
    int co = idx & 31;
    int ck = idx >> 5;
    g_wTo[idx] = (co < 27) ? w_off[co*CK + ck] : 0.0f;
}

// ---- 3. reorder deconv weights: wT2[tap*16384 + i*128 + o] = w_up[i][o][ky][kx] ----
__global__ void k_reorder_wup(const float* __restrict__ w_up) {
    int idx = blockIdx.x * blockDim.x + threadIdx.x;
    if (idx >= 16*COUT*COUT) return;
    int tap = idx >> 14;
    int rem = idx & 16383;
    int i = rem >> 7;
    int o = rem & 127;
    g_wT2[idx] = w_up[(i*COUT + o)*16 + tap];
}

// ---- 4. offset conv, shared-tile version ----
// block = 256 threads, 8 pixels in a row. Tile: 3 rows x 10 cols x 256 ch.
__global__ void k_offconv(const float* __restrict__ b_off) {
    __shared__ float tile[CIN*30];        // tile[c*30 + r*10 + col], 30 KB
    __shared__ float sred[32*8*8];        // [co][slice][p], 8 KB

    int tid = threadIdx.x;
    int pixbase = blockIdx.x * 8;
    int b  = pixbase >> 12;
    int h  = (pixbase >> 6) & 63;
    int w0 = pixbase & 63;

    // gather: thread = channel
    {
        int c = tid;
        const float* xb = g_xn + (size_t)b*HH*WW*CIN;
        #pragma unroll
        for (int r = 0; r < 3; r++) {
            int yy = h - 1 + r;
            bool vy = (yy >= 0 && yy < HH);
            #pragma unroll
            for (int col = 0; col < 10; col++) {
                int xx = w0 - 1 + col;
                float v = 0.f;
                if (vy && xx >= 0 && xx < WW) v = xb[(yy*WW + xx)*CIN + c];
                tile[c*30 + r*10 + col] = v;
            }
        }
    }
    __syncthreads();

    // matvec: o = tid&31 (27 valid co), slice = tid>>5 splits channels
    {
        int o = tid & 31;
        int slice = tid >> 5;
        float acc[8] = {0,0,0,0,0,0,0,0};
        for (int cl = 0; cl < 32; cl++) {
            int c = slice*32 + cl;
            const float* tc = tile + c*30;
            float t[30];
            #pragma unroll
            for (int j = 0; j < 30; j++) t[j] = tc[j];
            const float* wp = g_wTo + (size_t)(c*9)*32 + o;
            #pragma unroll
            for (int ky = 0; ky < 3; ky++) {
                #pragma unroll
                for (int kx = 0; kx < 3; kx++) {
                    float wv = wp[(ky*3 + kx)*32];
                    #pragma unroll
                    for (int p = 0; p < 8; p++)
                        acc[p] += t[ky*10 + kx + p] * wv;
                }
            }
        }
        #pragma unroll
        for (int p = 0; p < 8; p++)
            sred[(o*8 + slice)*8 + p] = acc[p];
    }
    __syncthreads();

    // reduce 8 slices, add bias, write
    if (tid < 27*8) {
        int co = tid >> 3;
        int p  = tid & 7;
        float s = b_off[co];
        #pragma unroll
        for (int sl = 0; sl < 8; sl++)
            s += sred[(co*8 + sl)*8 + p];
        g_om[((b*27 + co)*HH + h)*WW + w0 + p] = s;
    }
}

// ---- 5. modulated deformable conv ----
// block = 256 threads, 8 pixels in a row; dynamic smem; f32x2 matvec
#define DCN_NPIX 8
#define DCN_SVAL_BYTES (CK*DCN_NPIX*4)                 // 73728
#define DCN_SRED_BYTES (COUT*4*8)                      // 4096 (ull[o][4])
#define DCN_SWT_BYTES  (72*4*4)                        // 1152
#define DCN_IDX_BYTES  (72*4*4)                        // 1152 (4 int arrays of 72)
#define DCN_SMEM (DCN_SVAL_BYTES + DCN_SRED_BYTES + DCN_SWT_BYTES + DCN_IDX_BYTES)

__global__ void k_dcn(const float* __restrict__ b_dcn) {
    extern __shared__ char dsm[];
    float* sval = (float*)dsm;                                    // [ck][8]
    unsigned long long* sredU = (unsigned long long*)(dsm + DCN_SVAL_BYTES);  // [o][4]
    float (*swt)[4] = (float(*)[4])(dsm + DCN_SVAL_BYTES + DCN_SRED_BYTES);
    int* sy0 = (int*)(dsm + DCN_SVAL_BYTES + DCN_SRED_BYTES + DCN_SWT_BYTES);
    int* sy1 = sy0 + 72;
    int* sx0 = sy1 + 72;
    int* sx1 = sx0 + 72;

    int tid = threadIdx.x;
    int pixbase = blockIdx.x * DCN_NPIX;
    int b  = pixbase >> 12;
    int h  = (pixbase >> 6) & 63;
    int w0 = pixbase & 63;

    if (tid < 72) {
        int p = tid / 9, k = tid % 9;
        int w = w0 + p;
        int ky = k / 3, kx = k % 3;
        const float* omb = g_om + (b*27)*4096 + h*64 + w;
        float dy = omb[(2*k)*4096];
        float dx = omb[(2*k + 1)*4096];
        float mm = omb[(18 + k)*4096];
        float mask = 1.0f / (1.0f + expf(-mm));
        float ys = (float)(h - 1 + ky) + dy;
        float xs = (float)(w - 1 + kx) + dx;
        float y0f = floorf(ys), x0f = floorf(xs);
        float ly = ys - y0f, lx = xs - x0f;
        int y0 = (int)y0f, x0 = (int)x0f;
        int y1i = y0 + 1, x1i = x0 + 1;
        float vy0 = (y0 >= 0 && y0 < 64) ? 1.0f : 0.0f;
        float vy1 = (y1i >= 0 && y1i < 64) ? 1.0f : 0.0f;
        float vx0 = (x0 >= 0 && x0 < 64) ? 1.0f : 0.0f;
        float vx1 = (x1i >= 0 && x1i < 64) ? 1.0f : 0.0f;
        swt[tid][0] = (1.0f - ly)*(1.0f - lx)*mask*vy0*vx0;
        swt[tid][1] = (1.0f - ly)*lx       *mask*vy0*vx1;
        swt[tid][2] = ly       *(1.0f - lx)*mask*vy1*vx0;
        swt[tid][3] = ly*lx                *mask*vy1*vx1;
        sy0[tid] = min(max(y0, 0), 63);
        sy1[tid] = min(max(y1i, 0), 63);
        sx0[tid] = min(max(x0, 0), 63);
        sx1[tid] = min(max(x1i, 0), 63);
    }
    __syncthreads();

    // gather: c = tid (0..255), 72 (pixel,tap) combos
    {
        int c = tid;
        const float* xb = g_xn + (size_t)b*HH*WW*CIN;
        #pragma unroll 4
        for (int pk = 0; pk < 72; pk++) {
            int p = pk / 9, k = pk % 9;
            float v00 = xb[(sy0[pk]*64 + sx0[pk])*CIN + c];
            float v01 = xb[(sy0[pk]*64 + sx1[pk])*CIN + c];
            float v10 = xb[(sy1[pk]*64 + sx0[pk])*CIN + c];
            float v11 = xb[(sy1[pk]*64 + sx1[pk])*CIN + c];
            float v = swt[pk][0]*v00 + swt[pk][1]*v01 + swt[pk][2]*v10 + swt[pk][3]*v11;
            sval[(c*9 + k)*DCN_NPIX + p] = v;
        }
    }
    __syncthreads();

    // matvec: o = tid&127, halves split ck; 8 pixel accs as 4 f32x2
    int o = tid & 127;
    int half = tid >> 7;
    unsigned long long a01 = 0ull, a23 = 0ull, a45 = 0ull, a67 = 0ull;
    const float* wp = g_wT + o;
    int ck0 = half * (CK/2);
    #pragma unroll 4
    for (int ck = ck0; ck < ck0 + CK/2; ck++) {
        float wv = wp[ck*COUT];
        unsigned long long ww = pack2(wv);
        const ulonglong2* vp = (const ulonglong2*)(sval + ck*DCN_NPIX);
        ulonglong2 v0 = vp[0];
        ulonglong2 v1 = vp[1];
        fma2(a01, v0.x, ww);
        fma2(a23, v0.y, ww);
        fma2(a45, v1.x, ww);
        fma2(a67, v1.y, ww);
    }
    if (half == 1) {
        sredU[o*4+0] = a01; sredU[o*4+1] = a23;
        sredU[o*4+2] = a45; sredU[o*4+3] = a67;
    }
    __syncthreads();
    if (half == 0) {
        unsigned long long bb = pack2(b_dcn[o]);
        add2(a01, sredU[o*4+0]); add2(a01, bb);
        add2(a23, sredU[o*4+1]); add2(a23, bb);
        add2(a45, sredU[o*4+2]); add2(a45, bb);
        add2(a67, sredU[o*4+3]); add2(a67, bb);
        float2 f;
        f = unpack2(a01);
        g_y1[(pixbase+0)*COUT + o] = f.x;
        g_y1[(pixbase+1)*COUT + o] = f.y;
        f = unpack2(a23);
        g_y1[(pixbase+2)*COUT + o] = f.x;
        g_y1[(pixbase+3)*COUT + o] = f.y;
        f = unpack2(a45);
        g_y1[(pixbase+4)*COUT + o] = f.x;
        g_y1[(pixbase+5)*COUT + o] = f.y;
        f = unpack2(a67);
        g_y1[(pixbase+6)*COUT + o] = f.x;
        g_y1[(pixbase+7)*COUT + o] = f.y;
    }
}

// ---- 6. BN1 partial sums over y1 ----
__global__ void k_bn1_part() {
    int c = threadIdx.x;
    int base = blockIdx.x * 64;      // 256 blocks * 64 pixels = 16384
    float s = 0.f, ss = 0.f;
    for (int i = 0; i < 64; i++) {
        float v = g_y1[(base + i)*COUT + c];
        s += v; ss += v*v;
    }
    g_part1[blockIdx.x*2*COUT + c] = s;
    g_part1[blockIdx.x*2*COUT + COUT + c] = ss;
}

__global__ void k_bn1_fin(const float* __restrict__ gamma,
                          const float* __restrict__ beta) {
    int c = threadIdx.x;
    float s = 0.f, ss = 0.f;
    for (int j = 0; j < 256; j++) {
        s  += g_part1[j*2*COUT + c];
        ss += g_part1[j*2*COUT + COUT + c];
    }
    const float invN = 1.0f / 16384.0f;
    float mean = s * invN;
    float var = ss * invN - mean*mean;
    float rstd = rsqrtf(var + 1e-5f);
    float sc = gamma[c] * rstd;
    g_scale1[c] = sc;
    g_shift1[c] = beta[c] - mean*sc;
}

// ---- 7. transposed conv (reads y1, applies BN1+ReLU on the fly) ----
// block = 256 threads, 16 output pixels in a row; f32x2 matvec
__global__ void k_deconv() {
    __shared__ float sval[4*COUT*2*8];     // [j][i][group][q], 32 KB

    int tid = threadIdx.x;
    int pixbase = blockIdx.x * 16;
    int b   = pixbase >> 14;
    int oy  = (pixbase >> 7) & 127;
    int ox0 = pixbase & 127;
    int py  = (oy + 1) & 1;

    // gather: 16 pixels x 4 taps x 128 channels
    {
        int c = tid & 127;
        int sub = tid >> 7;
        #pragma unroll
        for (int it = 0; it < 32; it++) {
            int pair = it*2 + sub;       // 0..63 over (p, j)
            int p = pair >> 2;
            int j = pair & 3;
            int jy = j >> 1, jx = j & 1;
            int ox = ox0 + p;
            int px = (ox + 1) & 1;
            int ky = py + jy*2;
            int kx = px + jx*2;
            int ty = oy + 1 - ky;     // = 2*iy
            int tx = ox + 1 - kx;     // = 2*ix
            float v = 0.f;
            if (ty >= 0 && ty <= 126 && tx >= 0 && tx <= 126) {
                int iy = ty >> 1, ix = tx >> 1;
                float raw = g_y1[((b*HH + iy)*WW + ix)*COUT + c];
                v = fmaxf(g_scale1[c]*raw + g_shift1[c], 0.f);
            }
            int group = p & 1, q = p >> 1;
            sval[((j*COUT + c)*2 + group)*8 + q] = v;
        }
    }
    __syncthreads();

    // matvec: o = tid&127, group = parity; 8 q accs as 4 f32x2
    int o = tid & 127;
    int group = tid >> 7;
    int px = (ox0 + group + 1) & 1;
    unsigned long long a01 = 0ull, a23 = 0ull, a45 = 0ull, a67 = 0ull;
    #pragma unroll
    for (int j = 0; j < 4; j++) {
        int ky = py + (j >> 1)*2;
        int kx = px + (j & 1)*2;
        int tap = ky*4 + kx;
        const float* wp = g_wT2 + tap*COUT*COUT + o;
        #pragma unroll 4
        for (int i = 0; i < COUT; i++) {
            float wv = wp[i*COUT];
            unsigned long long ww = pack2(wv);
            const ulonglong2* vp =
                (const ulonglong2*)(sval + ((j*COUT + i)*2 + group)*8);
            ulonglong2 v0 = vp[0];
            ulonglong2 v1 = vp[1];
            fma2(a01, v0.x, ww);
            fma2(a23, v0.y, ww);
            fma2(a45, v1.x, ww);
            fma2(a67, v1.y, ww);
        }
    }
    float* zp = g_z + (size_t)(pixbase + group)*COUT + o;
    float2 f;
    f = unpack2(a01);
    zp[0*2*COUT] = f.x;  zp[1*2*COUT] = f.y;
    f = unpack2(a23);
    zp[2*2*COUT] = f.x;  zp[3*2*COUT] = f.y;
    f = unpack2(a45);
    zp[4*2*COUT] = f.x;  zp[5*2*COUT] = f.y;
    f = unpack2(a67);
    zp[6*2*COUT] = f.x;  zp[7*2*COUT] = f.y;
}

// ---- 8. BN2 partial sums over z ----
__global__ void k_bn2_part() {
    int c = threadIdx.x;
    int base = blockIdx.x * 128;     // 512 blocks * 128 pixels = 65536
    float s = 0.f, ss = 0.f;
    for (int i = 0; i < 128; i++) {
        float v = g_z[(size_t)(base + i)*COUT + c];
        s += v; ss += v*v;
    }
    g_part2[blockIdx.x*2*COUT + c] = s;
    g_part2[blockIdx.x*2*COUT + COUT + c] = ss;
}

__global__ void k_bn2_fin(const float* __restrict__ gamma,
                          const float* __restrict__ beta) {
    int c = threadIdx.x;
    float s = 0.f, ss = 0.f;
    for (int j = 0; j < 512; j++) {
        s  += g_part2[j*2*COUT + c];
        ss += g_part2[j*2*COUT + COUT + c];
    }
    const float invN = 1.0f / 65536.0f;
    float mean = s * invN;
    float var = ss * invN - mean*mean;
    float rstd = rsqrtf(var + 1e-5f);
    float sc = gamma[c] * rstd;
    g_scale2[c] = sc;
    g_shift2[c] = beta[c] - mean*sc;
}

// ---- 9. final: BN2 + ReLU + NHWC -> NCHW transpose into d_out ----
__global__ void k_final(float* __restrict__ out) {
    __shared__ float tile[32][33];
    int s0 = blockIdx.x * 32;        // 512 tiles over 16384 spatial
    int c0 = blockIdx.y * 32;        // 4 tiles over 128 channels
    int b  = blockIdx.z;
    #pragma unroll
    for (int i = 0; i < 4; i++) {
        int srow = threadIdx.y + i*8;
        int ch = c0 + threadIdx.x;
        float v = g_z[((size_t)b*16384 + s0 + srow)*COUT + ch];
        tile[srow][threadIdx.x] = fmaxf(g_scale2[ch]*v + g_shift2[ch], 0.f);
    }
    __syncthreads();
    #pragma unroll
    for (int i = 0; i < 4; i++) {
        int crow = threadIdx.y + i*8;
        out[((size_t)b*COUT + c0 + crow)*16384 + s0 + threadIdx.x] = tile[threadIdx.x][crow];
    }
}

extern "C" void kernel_launch(void* const* d_in, const int* in_sizes, int n_in,
                              void* d_out, int out_size) {
    const float* x      = (const float*)d_in[0];
    const float* w_off  = (const float*)d_in[1];
    const float* b_off  = (const float*)d_in[2];
    const float* w_dcn  = (const float*)d_in[3];
    const float* b_dcn  = (const float*)d_in[4];
    const float* gamma1 = (const float*)d_in[5];
    const float* beta1  = (const float*)d_in[6];
    const float* w_up   = (const float*)d_in[7];
    const float* gamma2 = (const float*)d_in[8];
    const float* beta2  = (const float*)d_in[9];
    float* out = (float*)d_out;

    cudaFuncSetAttribute(k_dcn, cudaFuncAttributeMaxDynamicSharedMemorySize, DCN_SMEM);

    k_transpose_x<<<(NB*HH*WW*CIN + 255)/256, 256>>>(x);
    k_reorder_wdcn<<<(CK*COUT + 255)/256, 256>>>(w_dcn);
    k_reorder_woff<<<(CK*32 + 255)/256, 256>>>(w_off);
    k_reorder_wup<<<(16*COUT*COUT + 255)/256, 256>>>(w_up);
    k_offconv<<<NB*HH*WW/8, 256>>>(b_off);
    k_dcn<<<NB*HH*WW/DCN_NPIX, 256, DCN_SMEM>>>(b_dcn);
    k_bn1_part<<<256, COUT>>>();
    k_bn1_fin<<<1, COUT>>>(gamma1, beta1);
    k_deconv<<<NB*HO*WO/16, 256>>>();
    k_bn2_part<<<512, COUT>>>();
    k_bn2_fin<<<1, COUT>>>(gamma2, beta2);
    k_final<<<dim3(512, 4, NB), dim3(32, 8)>>>(out);
}

// round 11
// speedup vs baseline: 1.5930x; 1.5930x over previous
#include <cuda_runtime.h>
#include <math.h>

#define NB 4
#define CIN 256
#define COUT 128
#define HH 64
#define WW 64
#define HO 128
#define WO 128
#define KK9 9
#define CK (CIN*KK9)   // 2304

#define PADV 68        // sV row stride (floats), 16B aligned, modest STS conflicts
#define PADW 132       // sW row stride (floats)

// ---- scratch (device globals; no allocation) ----
__device__ float g_xn[NB*HH*WW*CIN];        // x in NHWC, 16 MB
__device__ float g_om[NB*27*HH*WW];         // offset conv output, NCHW
__device__ float g_wT[CK*COUT];             // dcn weights (ck=k*256+c, o)
__device__ float g_wTo[CK*32];              // offconv weights (c*9+k, co) padded 27->32
__device__ float g_wT2[16*COUT*COUT];       // deconv weights (tap, i, o)
__device__ float g_y1[NB*HH*WW*COUT];       // dcn output NHWC (pre-BN)
__device__ float g_z[NB*HO*WO*COUT];        // deconv output NHWC (pre-BN)
__device__ float g_part1[256*2*COUT];
__device__ float g_part2[512*2*COUT];
__device__ float g_scale1[COUT], g_shift1[COUT];
__device__ float g_scale2[COUT], g_shift2[COUT];

// ---- packed fp32x2 helpers (sm_103a FFMA2) ----
__device__ __forceinline__ unsigned long long pack2(float v) {
    unsigned long long r;
    asm("mov.b64 %0, {%1, %1};" : "=l"(r) : "f"(v));
    return r;
}
__device__ __forceinline__ void fma2(unsigned long long& a, unsigned long long v, unsigned long long w) {
    asm("fma.rn.f32x2 %0, %1, %2, %0;" : "+l"(a) : "l"(v), "l"(w));
}
__device__ __forceinline__ float2 unpack2(unsigned long long a) {
    float2 f;
    asm("mov.b64 {%0, %1}, %2;" : "=f"(f.x), "=f"(f.y) : "l"(a));
    return f;
}

// shared 64ck x (64pix x 128o) tile-multiply: 4 o x 8 pix per thread
__device__ __forceinline__ void mm_tile(const float* sV, const float* sW,
                                        int og, int pg,
                                        unsigned long long acc[4][4]) {
    #pragma unroll 4
    for (int ck = 0; ck < 64; ck++) {
        const float* vrow = sV + ck*PADV + pg*8;
        ulonglong2 va = *(const ulonglong2*)(vrow);
        ulonglong2 vb = *(const ulonglong2*)(vrow + 4);
        float4 wq = *(const float4*)(sW + ck*PADW + og*4);
        unsigned long long w0 = pack2(wq.x), w1 = pack2(wq.y);
        unsigned long long w2 = pack2(wq.z), w3 = pack2(wq.w);
        fma2(acc[0][0], va.x, w0); fma2(acc[0][1], va.y, w0);
        fma2(acc[0][2], vb.x, w0); fma2(acc[0][3], vb.y, w0);
        fma2(acc[1][0], va.x, w1); fma2(acc[1][1], va.y, w1);
        fma2(acc[1][2], vb.x, w1); fma2(acc[1][3], vb.y, w1);
        fma2(acc[2][0], va.x, w2); fma2(acc[2][1], va.y, w2);
        fma2(acc[2][2], vb.x, w2); fma2(acc[2][3], vb.y, w2);
        fma2(acc[3][0], va.x, w3); fma2(acc[3][1], va.y, w3);
        fma2(acc[3][2], vb.x, w3); fma2(acc[3][3], vb.y, w3);
    }
}

// ---- 0. merged weight reorders ----
__global__ void k_prep_w(const float* __restrict__ w_dcn,
                         const float* __restrict__ w_off,
                         const float* __restrict__ w_up) {
    int idx = blockIdx.x * blockDim.x + threadIdx.x;
    if (idx < CK*COUT) {              // dcn: wT[(k*256+c)*128 + o] = w_dcn[o][c][k]
        int o = idx & 127;
        int ck = idx >> 7;
        int k = ck >> 8;
        int c = ck & 255;
        g_wT[idx] = w_dcn[o*CK + c*9 + k];
    }
    if (idx < CK*32) {                // offconv: wTo[(c*9+k)*32 + co]
        int co = idx & 31;
        int ck = idx >> 5;
        g_wTo[idx] = (co < 27) ? w_off[co*CK + ck] : 0.0f;
    }
    if (idx < 16*COUT*COUT) {         // deconv: wT2[tap][i][o]
        int tap = idx >> 14;
        int rem = idx & 16383;
        int i = rem >> 7;
        int o = rem & 127;
        g_wT2[idx] = w_up[(i*COUT + o)*16 + tap];
    }
}

// ---- 1. transpose x NCHW -> NHWC ----
__global__ void k_transpose_x(const float* __restrict__ x) {
    int idx = blockIdx.x * blockDim.x + threadIdx.x;
    if (idx >= NB*HH*WW*CIN) return;
    int c = idx & (CIN-1);
    int pix = idx >> 8;
    int b = pix >> 12;
    int h = (pix >> 6) & 63;
    int w = pix & 63;
    g_xn[idx] = x[((b*CIN + c)*HH + h)*WW + w];
}

// ---- 2. offset conv, shared-tile version ----
__global__ void k_offconv(const float* __restrict__ b_off) {
    __shared__ float tile[CIN*30];
    __shared__ float sred[32*8*8];

    int tid = threadIdx.x;
    int pixbase = blockIdx.x * 8;
    int b  = pixbase >> 12;
    int h  = (pixbase >> 6) & 63;
    int w0 = pixbase & 63;

    {
        int c = tid;
        const float* xb = g_xn + (size_t)b*HH*WW*CIN;
        #pragma unroll
        for (int r = 0; r < 3; r++) {
            int yy = h - 1 + r;
            bool vy = (yy >= 0 && yy < HH);
            #pragma unroll
            for (int col = 0; col < 10; col++) {
                int xx = w0 - 1 + col;
                float v = 0.f;
                if (vy && xx >= 0 && xx < WW) v = xb[(yy*WW + xx)*CIN + c];
                tile[c*30 + r*10 + col] = v;
            }
        }
    }
    __syncthreads();

    {
        int o = tid & 31;
        int slice = tid >> 5;
        float acc[8] = {0,0,0,0,0,0,0,0};
        for (int cl = 0; cl < 32; cl++) {
            int c = slice*32 + cl;
            const float* tc = tile + c*30;
            float t[30];
            #pragma unroll
            for (int j = 0; j < 30; j++) t[j] = tc[j];
            const float* wp = g_wTo + (size_t)(c*9)*32 + o;
            #pragma unroll
            for (int ky = 0; ky < 3; ky++) {
                #pragma unroll
                for (int kx = 0; kx < 3; kx++) {
                    float wv = wp[(ky*3 + kx)*32];
                    #pragma unroll
                    for (int p = 0; p < 8; p++)
                        acc[p] += t[ky*10 + kx + p] * wv;
                }
            }
        }
        #pragma unroll
        for (int p = 0; p < 8; p++)
            sred[(o*8 + slice)*8 + p] = acc[p];
    }
    __syncthreads();

    if (tid < 27*8) {
        int co = tid >> 3;
        int p  = tid & 7;
        float s = b_off[co];
        #pragma unroll
        for (int sl = 0; sl < 8; sl++)
            s += sred[(co*8 + sl)*8 + p];
        g_om[((b*27 + co)*HH + h)*WW + w0 + p] = s;
    }
}

// ---- 3. DCN as K-tiled GEMM with fused deformable gather ----
// block: M=64 pixels (one (b,h) row) x N=128 outputs. K = 2304 in 36 tiles of 64.
// dyn smem: sW[64][PADW] | sV[64][PADV] | swtA[9*64*4] | soffA[9*64*4]
#define DCN_SW_F   (64*PADW)                 // 8448 floats
#define DCN_SV_F   (64*PADV)                 // 4352
#define DCN_WT_F   (9*64*4)                  // 2304
#define DCN_SMEM_B ((DCN_SW_F + DCN_SV_F + DCN_WT_F + DCN_WT_F) * 4)   // 69632 B

__global__ void k_dcn_gemm(const float* __restrict__ b_dcn) {
    extern __shared__ float dsm[];
    float* sW   = dsm;
    float* sV   = dsm + DCN_SW_F;
    float* swtA = dsm + DCN_SW_F + DCN_SV_F;
    int*   soffA = (int*)(dsm + DCN_SW_F + DCN_SV_F + DCN_WT_F);

    int t = threadIdx.x;
    int blk = blockIdx.x;          // 256 blocks
    int b = blk >> 6;
    int h = blk & 63;
    int pixbase = blk * 64;        // = b*4096 + h*64

    // meta: per (k, w): 4 corner weights + 4 clamped offsets
    for (int idx = t; idx < 576; idx += 256) {
        int k = idx >> 6, w = idx & 63;
        int ky = k / 3, kx = k % 3;
        const float* omb = g_om + (b*27)*4096 + h*64 + w;
        float dy = omb[(2*k)*4096];
        float dx = omb[(2*k + 1)*4096];
        float mm = omb[(18 + k)*4096];
        float mask = 1.0f / (1.0f + expf(-mm));
        float ys = (float)(h - 1 + ky) + dy;
        float xs = (float)(w - 1 + kx) + dx;
        float y0f = floorf(ys), x0f = floorf(xs);
        float ly = ys - y0f, lx = xs - x0f;
        int y0 = (int)y0f, x0 = (int)x0f;
        int y1i = y0 + 1, x1i = x0 + 1;
        float vy0 = (y0  >= 0 && y0  < 64) ? 1.0f : 0.0f;
        float vy1 = (y1i >= 0 && y1i < 64) ? 1.0f : 0.0f;
        float vx0 = (x0  >= 0 && x0  < 64) ? 1.0f : 0.0f;
        float vx1 = (x1i >= 0 && x1i < 64) ? 1.0f : 0.0f;
        swtA[idx*4+0] = (1.0f-ly)*(1.0f-lx)*mask*vy0*vx0;
        swtA[idx*4+1] = (1.0f-ly)*lx       *mask*vy0*vx1;
        swtA[idx*4+2] = ly       *(1.0f-lx)*mask*vy1*vx0;
        swtA[idx*4+3] = ly*lx              *mask*vy1*vx1;
        int y0c = min(max(y0, 0), 63),  y1c = min(max(y1i, 0), 63);
        int x0c = min(max(x0, 0), 63),  x1c = min(max(x1i, 0), 63);
        soffA[idx*4+0] = (y0c*64 + x0c)*CIN;
        soffA[idx*4+1] = (y0c*64 + x1c)*CIN;
        soffA[idx*4+2] = (y1c*64 + x0c)*CIN;
        soffA[idx*4+3] = (y1c*64 + x1c)*CIN;
    }
    __syncthreads();

    const float* xb = g_xn + (size_t)b*HH*WW*CIN;
    int og = t & 31, pg = t >> 5;
    unsigned long long acc[4][4] = {{0ull,0ull,0ull,0ull},{0ull,0ull,0ull,0ull},
                                    {0ull,0ull,0ull,0ull},{0ull,0ull,0ull,0ull}};

    for (int kt = 0; kt < 36; kt++) {
        // stage W tile (64 ck x 128 o)
        #pragma unroll
        for (int i = 0; i < 8; i++) {
            int f4 = t + i*256;
            int ckl = f4 >> 5, of4 = f4 & 31;
            float4 wv = *(const float4*)(g_wT + (size_t)(kt*64 + ckl)*COUT + of4*4);
            *(float4*)(sW + ckl*PADW + of4*4) = wv;
        }
        // gather V tile (64 c x 64 pix), transposed to [ck][pix]
        {
            int k = kt >> 2;
            int cbase = (kt & 3) * 64;
            int c_l = t & 63, mg = t >> 6;
            const float* xc = xb + cbase + c_l;
            #pragma unroll
            for (int i = 0; i < 16; i++) {
                int m = i*4 + mg;
                const float* wt4 = swtA + (k*64 + m)*4;
                const int*   of4 = soffA + (k*64 + m)*4;
                float v = wt4[0]*xc[of4[0]] + wt4[1]*xc[of4[1]]
                        + wt4[2]*xc[of4[2]] + wt4[3]*xc[of4[3]];
                sV[c_l*PADV + m] = v;
            }
        }
        __syncthreads();
        mm_tile(sV, sW, og, pg, acc);
        __syncthreads();
    }

    // epilogue: add bias, write y1 NHWC
    int obase = og * 4;
    float b0 = b_dcn[obase+0], b1 = b_dcn[obase+1];
    float b2 = b_dcn[obase+2], b3 = b_dcn[obase+3];
    #pragma unroll
    for (int pr = 0; pr < 4; pr++) {
        float2 p0 = unpack2(acc[0][pr]);
        float2 p1 = unpack2(acc[1][pr]);
        float2 p2 = unpack2(acc[2][pr]);
        float2 p3 = unpack2(acc[3][pr]);
        int pix0 = pixbase + pg*8 + pr*2;
        float4 qa = make_float4(p0.x+b0, p1.x+b1, p2.x+b2, p3.x+b3);
        float4 qb = make_float4(p0.y+b0, p1.y+b1, p2.y+b2, p3.y+b3);
        *(float4*)(g_y1 + (size_t)pix0*COUT + obase)     = qa;
        *(float4*)(g_y1 + (size_t)(pix0+1)*COUT + obase) = qb;
    }
}

// ---- 4. BN1 partial sums over y1 ----
__global__ void k_bn1_part() {
    int c = threadIdx.x;
    int base = blockIdx.x * 64;
    float s = 0.f, ss = 0.f;
    for (int i = 0; i < 64; i++) {
        float v = g_y1[(base + i)*COUT + c];
        s += v; ss += v*v;
    }
    g_part1[blockIdx.x*2*COUT + c] = s;
    g_part1[blockIdx.x*2*COUT + COUT + c] = ss;
}

__global__ void k_bn1_fin(const float* __restrict__ gamma,
                          const float* __restrict__ beta) {
    int c = threadIdx.x;
    float s = 0.f, ss = 0.f;
    for (int j = 0; j < 256; j++) {
        s  += g_part1[j*2*COUT + c];
        ss += g_part1[j*2*COUT + COUT + c];
    }
    const float invN = 1.0f / 16384.0f;
    float mean = s * invN;
    float var = ss * invN - mean*mean;
    float rstd = rsqrtf(var + 1e-5f);
    float sc = gamma[c] * rstd;
    g_scale1[c] = sc;
    g_shift1[c] = beta[c] - mean*sc;
}

// ---- 5. transposed conv as parity-class GEMM, BN1+ReLU fused in gather ----
// block: (b, oy, px) -> 64 output pixels of one parity class. K = 4 taps x 128 c,
// tiled as 8 x 64. dyn smem: sW[64][PADW] | sV[64][PADV]
#define DEC_SMEM_B ((DCN_SW_F + DCN_SV_F) * 4)     // 51200 B

__global__ void k_deconv_gemm() {
    extern __shared__ float dsm2[];
    float* sW = dsm2;
    float* sV = dsm2 + DCN_SW_F;

    int t = threadIdx.x;
    int blk = blockIdx.x;              // 1024 = b*256 + oy*2 + px
    int b  = blk >> 8;
    int oy = (blk >> 1) & 127;
    int px = blk & 1;
    int py = (oy + 1) & 1;
    int oxoff = (px + 1) & 1;          // ox = 2m + oxoff

    int og = t & 31, pg = t >> 5;
    unsigned long long acc[4][4] = {{0ull,0ull,0ull,0ull},{0ull,0ull,0ull,0ull},
                                    {0ull,0ull,0ull,0ull},{0ull,0ull,0ull,0ull}};
    const float* y1b = g_y1 + (size_t)b*HH*WW*COUT;

    for (int kt = 0; kt < 8; kt++) {
        int j = kt >> 1, chalf = kt & 1;
        int jy = j >> 1, jx = j & 1;
        int ky = py + 2*jy, kx = px + 2*jx;
        int tap = ky*4 + kx;
        int ty = oy + 1 - ky;                // = 2*iy
        bool vy = (ty >= 0 && ty <= 126);
        int iy = ty >> 1;
        int ixoff = (1 - px) - jx;           // ix = m + ixoff

        // stage W tile
        #pragma unroll
        for (int i = 0; i < 8; i++) {
            int f4 = t + i*256;
            int cl = f4 >> 5, of4 = f4 & 31;
            float4 wv = *(const float4*)(g_wT2 + (size_t)tap*16384
                                         + (chalf*64 + cl)*COUT + of4*4);
            *(float4*)(sW + cl*PADW + of4*4) = wv;
        }
        // gather V tile with BN1 + ReLU
        {
            int c_l = t & 63, mg = t >> 6;
            int c = chalf*64 + c_l;
            float sc = g_scale1[c], sh = g_shift1[c];
            #pragma unroll
            for (int i = 0; i < 16; i++) {
                int m = i*4 + mg;
                int ix = m + ixoff;
                float v = 0.f;
                if (vy && ix >= 0 && ix < 64) {
                    float raw = y1b[(iy*64 + ix)*COUT + c];
                    v = fmaxf(sc*raw + sh, 0.f);
                }
                sV[c_l*PADV + m] = v;
            }
        }
        __syncthreads();
        mm_tile(sV, sW, og, pg, acc);
        __syncthreads();
    }

    // epilogue: write z (pre-BN2) NHWC
    int obase = og * 4;
    #pragma unroll
    for (int pr = 0; pr < 4; pr++) {
        float2 p0 = unpack2(acc[0][pr]);
        float2 p1 = unpack2(acc[1][pr]);
        float2 p2 = unpack2(acc[2][pr]);
        float2 p3 = unpack2(acc[3][pr]);
        int m0 = pg*8 + pr*2;
        int ox0 = 2*m0 + oxoff;
        int ox1 = ox0 + 2;
        size_t base0 = ((size_t)(b*128 + oy)*128 + ox0)*COUT + obase;
        size_t base1 = ((size_t)(b*128 + oy)*128 + ox1)*COUT + obase;
        *(float4*)(g_z + base0) = make_float4(p0.x, p1.x, p2.x, p3.x);
        *(float4*)(g_z + base1) = make_float4(p0.y, p1.y, p2.y, p3.y);
    }
}

// ---- 6. BN2 partial sums over z ----
__global__ void k_bn2_part() {
    int c = threadIdx.x;
    int base = blockIdx.x * 128;
    float s = 0.f, ss = 0.f;
    for (int i = 0; i < 128; i++) {
        float v = g_z[(size_t)(base + i)*COUT + c];
        s += v; ss += v*v;
    }
    g_part2[blockIdx.x*2*COUT + c] = s;
    g_part2[blockIdx.x*2*COUT + COUT + c] = ss;
}

__global__ void k_bn2_fin(const float* __restrict__ gamma,
                          const float* __restrict__ beta) {
    int c = threadIdx.x;
    float s = 0.f, ss = 0.f;
    for (int j = 0; j < 512; j++) {
        s  += g_part2[j*2*COUT + c];
        ss += g_part2[j*2*COUT + COUT + c];
    }
    const float invN = 1.0f / 65536.0f;
    float mean = s * invN;
    float var = ss * invN - mean*mean;
    float rstd = rsqrtf(var + 1e-5f);
    float sc = gamma[c] * rstd;
    g_scale2[c] = sc;
    g_shift2[c] = beta[c] - mean*sc;
}

// ---- 7. final: BN2 + ReLU + NHWC -> NCHW transpose into d_out ----
__global__ void k_final(float* __restrict__ out) {
    __shared__ float tile[32][33];
    int s0 = blockIdx.x * 32;
    int c0 = blockIdx.y * 32;
    int b  = blockIdx.z;
    #pragma unroll
    for (int i = 0; i < 4; i++) {
        int srow = threadIdx.y + i*8;
        int ch = c0 + threadIdx.x;
        float v = g_z[((size_t)b*16384 + s0 + srow)*COUT + ch];
        tile[srow][threadIdx.x] = fmaxf(g_scale2[ch]*v + g_shift2[ch], 0.f);
    }
    __syncthreads();
    #pragma unroll
    for (int i = 0; i < 4; i++) {
        int crow = threadIdx.y + i*8;
        out[((size_t)b*COUT + c0 + crow)*16384 + s0 + threadIdx.x] = tile[threadIdx.x][crow];
    }
}

extern "C" void kernel_launch(void* const* d_in, const int* in_sizes, int n_in,
                              void* d_out, int out_size) {
    const float* x      = (const float*)d_in[0];
    const float* w_off  = (const float*)d_in[1];
    const float* b_off  = (const float*)d_in[2];
    const float* w_dcn  = (const float*)d_in[3];
    const float* b_dcn  = (const float*)d_in[4];
    const float* gamma1 = (const float*)d_in[5];
    const float* beta1  = (const float*)d_in[6];
    const float* w_up   = (const float*)d_in[7];
    const float* gamma2 = (const float*)d_in[8];
    const float* beta2  = (const float*)d_in[9];
    float* out = (float*)d_out;

    cudaFuncSetAttribute(k_dcn_gemm,    cudaFuncAttributeMaxDynamicSharedMemorySize, DCN_SMEM_B);
    cudaFuncSetAttribute(k_deconv_gemm, cudaFuncAttributeMaxDynamicSharedMemorySize, DEC_SMEM_B);

    k_prep_w<<<(CK*COUT + 255)/256, 256>>>(w_dcn, w_off, w_up);      // idx 0
    k_transpose_x<<<(NB*HH*WW*CIN + 255)/256, 256>>>(x);             // idx 1
    k_offconv<<<NB*HH*WW/8, 256>>>(b_off);                           // idx 2
    k_dcn_gemm<<<NB*HH*WW/64, 256, DCN_SMEM_B>>>(b_dcn);             // idx 3 (profiled)
    k_bn1_part<<<256, COUT>>>();
    k_bn1_fin<<<1, COUT>>>(gamma1, beta1);
    k_deconv_gemm<<<NB*HO*2, 256, DEC_SMEM_B>>>();
    k_bn2_part<<<512, COUT>>>();
    k_bn2_fin<<<1, COUT>>>(gamma2, beta2);
    k_final<<<dim3(512, 4, NB), dim3(32, 8)>>>(out);
}